// round 15
// baseline (speedup 1.0000x reference)
#include <cuda_runtime.h>
#include <cstdint>

// Problem constants (fixed-shape variant)
#define BS 4
#define NQ 10000
#define NH 8
#define HD 32
#define NP 4
#define SH 100
#define SW 100

// value layout: [b][pix][h][d], pix = y*SW + x  (pixel stride = 256 floats = 64 float4)
// loc: [b][q][h][0][p][2]   aw: [b][q][h][0][p]   out: [b][q][h*HD+d]
//
// One warp = (b, q, head-group hg) covering heads hg*4..hg*4+3.
// Compute phase: lanes 0..15 each build ONE (head,point) package
// (4 masked weights float4 + 4 float4-unit offsets int4) -> smem.
// Consume phase: g = lane>>3 (head), sub = lane&7 (float4 slot). Per point:
// 2 broadcast LDS.128 + 4 LDG.128 (each 8-lane group hits one 128B line).
// __launch_bounds__(256, 7): regs<=36 -> 7 CTAs/SM (56 warps) to feed the
// under-busy L1tex pipe with more outstanding gathers.

__global__ __launch_bounds__(256, 7) void deform_attn_kernel_v8(
    const float* __restrict__ value,
    const float* __restrict__ loc,
    const float* __restrict__ aw,
    float* __restrict__ out)
{
    __shared__ float4 s_w[8][16];   // [warp-in-block][combo]
    __shared__ int4   s_o[8][16];

    const int tid  = threadIdx.x;
    const int wib  = tid >> 5;
    const int lane = tid & 31;
    const int warp = blockIdx.x * 8 + wib;

    const int hg = warp & 1;
    const int bq = warp >> 1;           // b*NQ + q
    const int b  = bq / NQ;

    // ---- compute phase: lane c = lane&15 builds one (head, point) combo
    {
        const int c   = lane & 15;      // head gc = c>>2, point pc = c&3
        const int idx = bq * (NH * NP) + (hg << 4) + c;

        const float2 l = __ldg(reinterpret_cast<const float2*>(loc) + idx);
        const float  w = __ldg(aw + idx);

        const float x = fmaf(l.x, (float)SW, -0.5f);
        const float y = fmaf(l.y, (float)SH, -0.5f);
        const int x0 = __float2int_rd(x);
        const int y0 = __float2int_rd(y);
        const float tx = x - (float)x0;
        const float ty = y - (float)y0;

        // factored weights: 6 mul/fma
        const float wy1 = ty * w;
        const float wy0 = w - wy1;
        float w00 = fmaf(-tx, wy0, wy0);
        float w10 = tx * wy0;
        float w01 = fmaf(-tx, wy1, wy1);
        float w11 = tx * wy1;

        const bool vx0 = (unsigned)x0       < (unsigned)SW;
        const bool vx1 = (unsigned)(x0 + 1) < (unsigned)SW;
        const bool vy0 = (unsigned)y0       < (unsigned)SH;
        const bool vy1 = (unsigned)(y0 + 1) < (unsigned)SH;

        if (!vx0) { w00 = 0.f; w01 = 0.f; }
        if (!vx1) { w10 = 0.f; w11 = 0.f; }
        if (!vy0) { w00 = 0.f; w10 = 0.f; }
        if (!vy1) { w01 = 0.f; w11 = 0.f; }

        // float4-unit offsets: pix*64 + head*8 (head = hg*4 + gc)
        const int hterm = ((hg << 2) + (c >> 2)) << 3;
        const int ra = (vy0 ? y0 : 0) * (SW * 64) + hterm;
        const int rb = (vy1 ? (y0 + 1) : 0) * (SW * 64) + hterm;
        const int ca = (vx0 ? x0 : 0) << 6;
        const int cb = (vx1 ? (x0 + 1) : 0) << 6;

        if (lane < 16) {
            s_w[wib][c] = make_float4(w00, w10, w01, w11);
            s_o[wib][c] = make_int4(ra + ca, ra + cb, rb + ca, rb + cb);
        }
    }
    __syncwarp();

    // ---- consume phase
    const int sub = lane & 7;
    const float4* __restrict__ vb =
        reinterpret_cast<const float4*>(value) +
        (size_t)b * (SH * SW * (NH * HD / 4)) + sub;

    const int srcbase = (lane >> 3) << 2;   // combos for my head: srcbase + p

    float4 accA = make_float4(0.f, 0.f, 0.f, 0.f);
    float4 accB = make_float4(0.f, 0.f, 0.f, 0.f);

#pragma unroll
    for (int p = 0; p < NP; ++p) {
        const float4 W = s_w[wib][srcbase + p];
        const int4   O = s_o[wib][srcbase + p];

        const float4 v00 = __ldg(vb + O.x);
        const float4 v10 = __ldg(vb + O.y);
        const float4 v01 = __ldg(vb + O.z);
        const float4 v11 = __ldg(vb + O.w);

        accA.x = fmaf(W.x, v00.x, accA.x); accA.y = fmaf(W.x, v00.y, accA.y);
        accA.z = fmaf(W.x, v00.z, accA.z); accA.w = fmaf(W.x, v00.w, accA.w);
        accB.x = fmaf(W.y, v10.x, accB.x); accB.y = fmaf(W.y, v10.y, accB.y);
        accB.z = fmaf(W.y, v10.z, accB.z); accB.w = fmaf(W.y, v10.w, accB.w);
        accA.x = fmaf(W.z, v01.x, accA.x); accA.y = fmaf(W.z, v01.y, accA.y);
        accA.z = fmaf(W.z, v01.z, accA.z); accA.w = fmaf(W.z, v01.w, accA.w);
        accB.x = fmaf(W.w, v11.x, accB.x); accB.y = fmaf(W.w, v11.y, accB.y);
        accB.z = fmaf(W.w, v11.z, accB.z); accB.w = fmaf(W.w, v11.w, accB.w);
    }

    float4 acc;
    acc.x = accA.x + accB.x;
    acc.y = accA.y + accB.y;
    acc.z = accA.z + accB.z;
    acc.w = accA.w + accB.w;

    // out float4 index: bq*64 + hg*32 + lane (contiguous per warp)
    reinterpret_cast<float4*>(out)[(size_t)bq * (NH * HD / 4) + (hg << 5) + lane] = acc;
}

extern "C" void kernel_launch(void* const* d_in, const int* in_sizes, int n_in,
                              void* d_out, int out_size)
{
    const float* value = (const float*)d_in[0];
    // d_in[1] = value_spatial_shapes (int64), unused
    const float* loc = (const float*)d_in[2];
    const float* aw = (const float*)d_in[3];
    float* out = (float*)d_out;

    const int total_warps = BS * NQ * (NH / 4);      // 80000
    const int threads = 256;
    const int blocks = total_warps * 32 / threads;   // 10000 (exact)

    deform_attn_kernel_v8<<<blocks, threads>>>(value, loc, aw, out);
}

// round 16
// speedup vs baseline: 1.0022x; 1.0022x over previous
#include <cuda_runtime.h>
#include <cstdint>

// Problem constants (fixed-shape variant)
#define BS 4
#define NQ 10000
#define NH 8
#define HD 32
#define NP 4
#define SH 100
#define SW 100

// value layout: [b][pix][h][d], pix = y*SW + x  (pixel stride = 256 floats = 64 float4)
// loc: [b][q][h][0][p][2]   aw: [b][q][h][0][p]   out: [b][q][h*HD+d]
//
// One warp = (b, q, head-group hg) covering heads hg*4..hg*4+3.
// Compute phase: lanes 0..15 each build ONE (head,point) package -> smem.
// Consume phase: g = lane>>3 (head), sub = lane&7 (float4 slot).
// Hand-pipelined: keep TWO points' gathers (8x LDG.128 = 32 data regs) in
// flight; FMA point p while issuing point p+2. __launch_bounds__(256,5)
// gives ptxas 48 regs for the deeper pipeline (v8 showed 32 regs kills MLP).

__global__ __launch_bounds__(256, 5) void deform_attn_kernel_v9(
    const float* __restrict__ value,
    const float* __restrict__ loc,
    const float* __restrict__ aw,
    float* __restrict__ out)
{
    __shared__ float4 s_w[8][16];   // [warp-in-block][combo]
    __shared__ int4   s_o[8][16];

    const int tid  = threadIdx.x;
    const int wib  = tid >> 5;
    const int lane = tid & 31;
    const int warp = blockIdx.x * 8 + wib;

    const int hg = warp & 1;
    const int bq = warp >> 1;           // b*NQ + q
    const int b  = bq / NQ;

    // ---- compute phase: lane c = lane&15 builds one (head, point) combo
    {
        const int c   = lane & 15;      // head gc = c>>2, point pc = c&3
        const int idx = bq * (NH * NP) + (hg << 4) + c;

        const float2 l = __ldg(reinterpret_cast<const float2*>(loc) + idx);
        const float  w = __ldg(aw + idx);

        const float x = fmaf(l.x, (float)SW, -0.5f);
        const float y = fmaf(l.y, (float)SH, -0.5f);
        const int x0 = __float2int_rd(x);
        const int y0 = __float2int_rd(y);
        const float tx = x - (float)x0;
        const float ty = y - (float)y0;

        // factored weights: 6 mul/fma
        const float wy1 = ty * w;
        const float wy0 = w - wy1;
        float w00 = fmaf(-tx, wy0, wy0);
        float w10 = tx * wy0;
        float w01 = fmaf(-tx, wy1, wy1);
        float w11 = tx * wy1;

        const bool vx0 = (unsigned)x0       < (unsigned)SW;
        const bool vx1 = (unsigned)(x0 + 1) < (unsigned)SW;
        const bool vy0 = (unsigned)y0       < (unsigned)SH;
        const bool vy1 = (unsigned)(y0 + 1) < (unsigned)SH;

        if (!vx0) { w00 = 0.f; w01 = 0.f; }
        if (!vx1) { w10 = 0.f; w11 = 0.f; }
        if (!vy0) { w00 = 0.f; w10 = 0.f; }
        if (!vy1) { w01 = 0.f; w11 = 0.f; }

        // float4-unit offsets: pix*64 + head*8 (head = hg*4 + gc)
        const int hterm = ((hg << 2) + (c >> 2)) << 3;
        const int ra = (vy0 ? y0 : 0) * (SW * 64) + hterm;
        const int rb = (vy1 ? (y0 + 1) : 0) * (SW * 64) + hterm;
        const int ca = (vx0 ? x0 : 0) << 6;
        const int cb = (vx1 ? (x0 + 1) : 0) << 6;

        if (lane < 16) {
            s_w[wib][c] = make_float4(w00, w10, w01, w11);
            s_o[wib][c] = make_int4(ra + ca, ra + cb, rb + ca, rb + cb);
        }
    }
    __syncwarp();

    // ---- consume phase (pipelined, depth 2 points) ----
    const int sub = lane & 7;
    const float4* __restrict__ vb =
        reinterpret_cast<const float4*>(value) +
        (size_t)b * (SH * SW * (NH * HD / 4)) + sub;

    const int sb = (lane >> 3) << 2;    // combos for my head: sb + p

    float4 accA = make_float4(0.f, 0.f, 0.f, 0.f);
    float4 accB = make_float4(0.f, 0.f, 0.f, 0.f);

    // prologue: issue points 0 and 1
    int4 Oa = s_o[wib][sb + 0];
    float4 a00 = __ldg(vb + Oa.x);
    float4 a10 = __ldg(vb + Oa.y);
    float4 a01 = __ldg(vb + Oa.z);
    float4 a11 = __ldg(vb + Oa.w);

    int4 Ob = s_o[wib][sb + 1];
    float4 b00 = __ldg(vb + Ob.x);
    float4 b10 = __ldg(vb + Ob.y);
    float4 b01 = __ldg(vb + Ob.z);
    float4 b11 = __ldg(vb + Ob.w);

    // ---- FMA p0, then reload a-regs with p2
    {
        const float4 W = s_w[wib][sb + 0];
        accA.x = fmaf(W.x, a00.x, accA.x); accA.y = fmaf(W.x, a00.y, accA.y);
        accA.z = fmaf(W.x, a00.z, accA.z); accA.w = fmaf(W.x, a00.w, accA.w);
        accB.x = fmaf(W.y, a10.x, accB.x); accB.y = fmaf(W.y, a10.y, accB.y);
        accB.z = fmaf(W.y, a10.z, accB.z); accB.w = fmaf(W.y, a10.w, accB.w);
        accA.x = fmaf(W.z, a01.x, accA.x); accA.y = fmaf(W.z, a01.y, accA.y);
        accA.z = fmaf(W.z, a01.z, accA.z); accA.w = fmaf(W.z, a01.w, accA.w);
        accB.x = fmaf(W.w, a11.x, accB.x); accB.y = fmaf(W.w, a11.y, accB.y);
        accB.z = fmaf(W.w, a11.z, accB.z); accB.w = fmaf(W.w, a11.w, accB.w);
    }
    Oa = s_o[wib][sb + 2];
    a00 = __ldg(vb + Oa.x);
    a10 = __ldg(vb + Oa.y);
    a01 = __ldg(vb + Oa.z);
    a11 = __ldg(vb + Oa.w);

    // ---- FMA p1, then reload b-regs with p3
    {
        const float4 W = s_w[wib][sb + 1];
        accA.x = fmaf(W.x, b00.x, accA.x); accA.y = fmaf(W.x, b00.y, accA.y);
        accA.z = fmaf(W.x, b00.z, accA.z); accA.w = fmaf(W.x, b00.w, accA.w);
        accB.x = fmaf(W.y, b10.x, accB.x); accB.y = fmaf(W.y, b10.y, accB.y);
        accB.z = fmaf(W.y, b10.z, accB.z); accB.w = fmaf(W.y, b10.w, accB.w);
        accA.x = fmaf(W.z, b01.x, accA.x); accA.y = fmaf(W.z, b01.y, accA.y);
        accA.z = fmaf(W.z, b01.z, accA.z); accA.w = fmaf(W.z, b01.w, accA.w);
        accB.x = fmaf(W.w, b11.x, accB.x); accB.y = fmaf(W.w, b11.y, accB.y);
        accB.z = fmaf(W.w, b11.z, accB.z); accB.w = fmaf(W.w, b11.w, accB.w);
    }
    Ob = s_o[wib][sb + 3];
    b00 = __ldg(vb + Ob.x);
    b10 = __ldg(vb + Ob.y);
    b01 = __ldg(vb + Ob.z);
    b11 = __ldg(vb + Ob.w);

    // ---- FMA p2
    {
        const float4 W = s_w[wib][sb + 2];
        accA.x = fmaf(W.x, a00.x, accA.x); accA.y = fmaf(W.x, a00.y, accA.y);
        accA.z = fmaf(W.x, a00.z, accA.z); accA.w = fmaf(W.x, a00.w, accA.w);
        accB.x = fmaf(W.y, a10.x, accB.x); accB.y = fmaf(W.y, a10.y, accB.y);
        accB.z = fmaf(W.y, a10.z, accB.z); accB.w = fmaf(W.y, a10.w, accB.w);
        accA.x = fmaf(W.z, a01.x, accA.x); accA.y = fmaf(W.z, a01.y, accA.y);
        accA.z = fmaf(W.z, a01.z, accA.z); accA.w = fmaf(W.z, a01.w, accA.w);
        accB.x = fmaf(W.w, a11.x, accB.x); accB.y = fmaf(W.w, a11.y, accB.y);
        accB.z = fmaf(W.w, a11.z, accB.z); accB.w = fmaf(W.w, a11.w, accB.w);
    }

    // ---- FMA p3
    {
        const float4 W = s_w[wib][sb + 3];
        accA.x = fmaf(W.x, b00.x, accA.x); accA.y = fmaf(W.x, b00.y, accA.y);
        accA.z = fmaf(W.x, b00.z, accA.z); accA.w = fmaf(W.x, b00.w, accA.w);
        accB.x = fmaf(W.y, b10.x, accB.x); accB.y = fmaf(W.y, b10.y, accB.y);
        accB.z = fmaf(W.y, b10.z, accB.z); accB.w = fmaf(W.y, b10.w, accB.w);
        accA.x = fmaf(W.z, b01.x, accA.x); accA.y = fmaf(W.z, b01.y, accA.y);
        accA.z = fmaf(W.z, b01.z, accA.z); accA.w = fmaf(W.z, b01.w, accA.w);
        accB.x = fmaf(W.w, b11.x, accB.x); accB.y = fmaf(W.w, b11.y, accB.y);
        accB.z = fmaf(W.w, b11.z, accB.z); accB.w = fmaf(W.w, b11.w, accB.w);
    }

    float4 acc;
    acc.x = accA.x + accB.x;
    acc.y = accA.y + accB.y;
    acc.z = accA.z + accB.z;
    acc.w = accA.w + accB.w;

    // out float4 index: bq*64 + hg*32 + lane (contiguous per warp)
    reinterpret_cast<float4*>(out)[(size_t)bq * (NH * HD / 4) + (hg << 5) + lane] = acc;
}

extern "C" void kernel_launch(void* const* d_in, const int* in_sizes, int n_in,
                              void* d_out, int out_size)
{
    const float* value = (const float*)d_in[0];
    // d_in[1] = value_spatial_shapes (int64), unused
    const float* loc = (const float*)d_in[2];
    const float* aw = (const float*)d_in[3];
    float* out = (float*)d_out;

    const int total_warps = BS * NQ * (NH / 4);      // 80000
    const int threads = 256;
    const int blocks = total_warps * 32 / threads;   // 10000 (exact)

    deform_attn_kernel_v9<<<blocks, threads>>>(value, loc, aw, out);
}